// round 14
// baseline (speedup 1.0000x reference)
#include <cuda_runtime.h>
#include <cuda_fp16.h>
#include <stdint.h>

#define N_TOK 65536
#define D     256
#define K     1024
#define NB    128              // codes per chunk
#define NCHUNK (K / NB)        // 8
#define CAP   16
#define WINDOW 2e-3f

// Scratch (no cudaMalloc allowed)
__device__ float g_counts[K];
__device__ float g_dw[K * D];
__device__ float g_cs[K];
__device__ unsigned long long g_loss;
__device__ __half g_xf[(size_t)N_TOK * D];   // tokens, row-major fp16
__device__ __half g_ct[D * K];               // codebook, k-major fp16: g_ct[k*K+code]

__device__ __forceinline__ unsigned fkey(float f) {
    unsigned b = __float_as_uint(f);
    return (b & 0x80000000u) ? ~b : (b ^ 0x80000000u);
}
__device__ __forceinline__ float fkeyinv(unsigned k) {
    unsigned b = (k & 0x80000000u) ? (k ^ 0x80000000u) : ~k;
    return __uint_as_float(b);
}

struct SmemT {
    __half As[D * 128];           // k-major tokens: As[k*128 + r]   (64 KB)
    __half Bs[D * NB];            // k-major codes:  Bs[k*128 + c]   (64 KB)
    float cssm[K];
    float rxs[128];
    unsigned runmin[128];
    int candn[128];
    unsigned short cand[128][CAP];
    int bestI[128];
    float bestD[128];
};                                // ~138 KB -> 1 CTA/SM

// ---------------------------------------------------------------------------
__global__ void vq_prep() {
    int i = blockIdx.x * blockDim.x + threadIdx.x;
    if (i < K * D) g_dw[i] = 0.0f;
    if (i < K)     g_counts[i] = 0.0f;
    if (i == 0)    g_loss = 0ull;
}

// fp32 -> fp16 row-major, 8 elems/thread
__global__ void vq_cvtH(const float* __restrict__ src, __half* __restrict__ dst) {
    size_t i = ((size_t)blockIdx.x * blockDim.x + threadIdx.x) * 8;
    float4 a = *(const float4*)(src + i);
    float4 b = *(const float4*)(src + i + 4);
    __half h[8];
    h[0] = __float2half_rn(a.x); h[1] = __float2half_rn(a.y);
    h[2] = __float2half_rn(a.z); h[3] = __float2half_rn(a.w);
    h[4] = __float2half_rn(b.x); h[5] = __float2half_rn(b.y);
    h[6] = __float2half_rn(b.z); h[7] = __float2half_rn(b.w);
    *(uint4*)(dst + i) = *(uint4*)h;
}

// Codebook -> k-major fp16 transpose (tiny: 256K elements)
__global__ void vq_cvtCT(const float* __restrict__ CB, __half* __restrict__ ct) {
    int code = blockIdx.x * 128 + (threadIdx.x >> 1);
    int off  = (threadIdx.x & 1) * 128;
    const float* row = CB + (size_t)code * D + off;
    #pragma unroll 4
    for (int j = 0; j < 128; j++)
        ct[(size_t)(off + j) * K + code] = __float2half_rn(row[j]);
}

// Codebook squared norms (exact fp32)
__global__ void vq_cs(const float* __restrict__ CB) {
    int w = (blockIdx.x * blockDim.x + threadIdx.x) >> 5;
    int lane = threadIdx.x & 31;
    if (w >= K) return;
    const float* row = CB + (size_t)w * D + lane * 8;
    float4 v0 = *(const float4*)row;
    float4 v1 = *(const float4*)(row + 4);
    float s = v0.x * v0.x + v0.y * v0.y + v0.z * v0.z + v0.w * v0.w
            + v1.x * v1.x + v1.y * v1.y + v1.z * v1.z + v1.w * v1.w;
    #pragma unroll
    for (int o = 16; o > 0; o >>= 1) s += __shfl_xor_sync(0xffffffffu, s, o);
    if (lane == 0) g_cs[w] = s;
}

// ---------------------------------------------------------------------------
// Main: HFMA2 fp16 filter + provable candidate window + exact fp32 rescore
// 256 thr; thread (tx=tid&15, ty=tid>>4) owns an 8(token)x8(code) tile.
// ---------------------------------------------------------------------------
__global__ __launch_bounds__(256, 1) void vq_dist(
    const float* __restrict__ X, const float* __restrict__ CB,
    float* __restrict__ outQ, float* __restrict__ outIdx)
{
    extern __shared__ char dsm[];
    SmemT& s = *(SmemT*)dsm;
    const int tid  = threadIdx.x;
    const int lane = tid & 31;
    const int wid  = tid >> 5;
    const int tx   = tid & 15;
    const int ty   = tid >> 4;
    const int tok0 = blockIdx.x * 128;

    if (tid < 128) { s.runmin[tid] = 0xFFFFFFFFu; s.candn[tid] = 0; }
    for (int i = tid; i < K; i += 256) s.cssm[i] = g_cs[i];

    // Stage A transposed: As[k*128 + r] (pair-packing for half2 is implicit)
    {
        int r = tid >> 1;
        int k0 = (tid & 1) * 128;
        const __half* src = g_xf + (size_t)(tok0 + r) * D + k0;
        #pragma unroll 8
        for (int k = 0; k < 128; k++)
            s.As[(size_t)(k0 + k) * 128 + r] = src[k];
    }
    // Exact per-token ||x||^2 (same order as passing rounds)
    if (tid < 128) {
        const float* xr = X + (size_t)(tok0 + tid) * D;
        float acc = 0.f;
        #pragma unroll 8
        for (int j = 0; j < D; j += 4) {
            float4 v = *(const float4*)(xr + j);
            acc += v.x * v.x; acc += v.y * v.y; acc += v.z * v.z; acc += v.w * v.w;
        }
        s.rxs[tid] = acc;
    }

    for (int ch = 0; ch < NCHUNK; ch++) {
        __syncthreads();
        // Stage B chunk: Bs[k*128 + c] from g_ct[k*K + ch*128 + c] (coalesced)
        {
            int r = tid >> 4, c16 = tid & 15;   // 16 thr per k-row
            #pragma unroll
            for (int p = 0; p < 16; p++) {
                int k = p * 16 + r;
                *(uint4*)&s.Bs[(size_t)k * 128 + c16 * 8] =
                    *(const uint4*)&g_ct[(size_t)k * K + ch * NB + c16 * 8];
            }
        }
        __syncthreads();

        // Level-2 half2 accumulators: 8 tokens x 4 half2 (8 codes)
        __half2 l2[8][4];
        #pragma unroll
        for (int r = 0; r < 8; r++)
            #pragma unroll
            for (int c = 0; c < 4; c++) l2[r][c] = __float2half2_rn(0.f);

        #pragma unroll 1
        for (int kb = 0; kb < D; kb += 32) {
            __half2 l1[8][4];
            #pragma unroll
            for (int r = 0; r < 8; r++)
                #pragma unroll
                for (int c = 0; c < 4; c++) l1[r][c] = __float2half2_rn(0.f);

            #pragma unroll 8
            for (int k2 = 0; k2 < 32; k2++) {
                int k = kb + k2;
                __half2 a2[4], b2[4];
                *(uint2*)(a2)     = *(const uint2*)&s.As[(size_t)k * 128 + ty * 8];
                *(uint2*)(a2 + 2) = *(const uint2*)&s.As[(size_t)k * 128 + ty * 8 + 4];
                *(uint2*)(b2)     = *(const uint2*)&s.Bs[(size_t)k * 128 + tx * 8];
                *(uint2*)(b2 + 2) = *(const uint2*)&s.Bs[(size_t)k * 128 + tx * 8 + 4];
                #pragma unroll
                for (int r = 0; r < 8; r++) {
                    __half2 ar = (r & 1) ? __high2half2(a2[r >> 1])
                                         : __low2half2(a2[r >> 1]);
                    #pragma unroll
                    for (int c = 0; c < 4; c++)
                        l1[r][c] = __hfma2(ar, b2[c], l1[r][c]);
                }
            }
            #pragma unroll
            for (int r = 0; r < 8; r++)
                #pragma unroll
                for (int c = 0; c < 4; c++) l2[r][c] = __hadd2(l2[r][c], l1[r][c]);
        }

        // e = cs - 2*s~ ; per-row chunk min -> smem runmin
        float eF[8][8];
        #pragma unroll
        for (int r = 0; r < 8; r++) {
            float rmin = 3.4e38f;
            #pragma unroll
            for (int c = 0; c < 4; c++) {
                int code = ch * NB + tx * 8 + 2 * c;
                float2 sf = __half22float2(l2[r][c]);
                float e0 = s.cssm[code]     - 2.f * sf.x;
                float e1 = s.cssm[code + 1] - 2.f * sf.y;
                eF[r][2 * c] = e0; eF[r][2 * c + 1] = e1;
                rmin = fminf(rmin, fminf(e0, e1));
            }
            #pragma unroll
            for (int o = 1; o <= 8; o <<= 1)
                rmin = fminf(rmin, __shfl_xor_sync(0xffffffffu, rmin, o));
            if ((lane & 15) == 0) atomicMin(&s.runmin[ty * 8 + r], fkey(rmin));
        }
        __syncthreads();

        // Collect candidates within WINDOW of the running min (superset:
        // runmin only decreases, so e <= final_min + W  =>  e <= cur_min + W)
        #pragma unroll
        for (int r = 0; r < 8; r++) {
            int row = ty * 8 + r;
            float thr = fkeyinv(s.runmin[row]) + WINDOW;
            #pragma unroll
            for (int c = 0; c < 8; c++) {
                if (eF[r][c] <= thr) {
                    int p = atomicAdd(&s.candn[row], 1);
                    if (p < CAP) s.cand[row][p] = (unsigned short)(ch * NB + tx * 8 + c);
                }
            }
        }
    }
    __syncthreads();

    // Exact fp32 rescore (warp per token, 16 tokens/warp; deterministic winner)
    for (int i = 0; i < 16; i++) {
        int t = wid * 16 + i;
        const float* xr = X + (size_t)(tok0 + t) * D + lane * 8;
        float4 xa = *(const float4*)xr;
        float4 xb = *(const float4*)(xr + 4);
        int nc = s.candn[t];
        bool full = (nc > CAP);
        int n = full ? K : nc;
        float rx = s.rxs[t];
        float best = 3.4e38f; int bk = K;
        for (int j = 0; j < n; j++) {
            int k = full ? j : (int)s.cand[t][j];
            const float* cr = CB + (size_t)k * D + lane * 8;
            float4 ca = *(const float4*)cr;
            float4 cb = *(const float4*)(cr + 4);
            float v = xa.x * ca.x;
            v = fmaf(xa.y, ca.y, v); v = fmaf(xa.z, ca.z, v); v = fmaf(xa.w, ca.w, v);
            v = fmaf(xb.x, cb.x, v); v = fmaf(xb.y, cb.y, v);
            v = fmaf(xb.z, cb.z, v); v = fmaf(xb.w, cb.w, v);
            #pragma unroll
            for (int o = 16; o > 0; o >>= 1) v += __shfl_xor_sync(0xffffffffu, v, o);
            float d = (rx + s.cssm[k]) - 2.f * v;
            if (d < best || (d == best && k < bk)) { best = d; bk = k; }
        }
        if (lane == 0) {
            s.bestI[t] = bk; s.bestD[t] = best;
            outIdx[tok0 + t] = (float)bk;
        }
    }
    __syncthreads();

    if (tid < 128) atomicAdd(&g_counts[s.bestI[tid]], 1.0f);
    if (tid == 0) {
        double sum = 0.0;
        for (int r = 0; r < 128; r++) sum += (double)s.bestD[r];
        atomicAdd(&g_loss, (unsigned long long)llrint(sum * 1048576.0));
    }
    __syncthreads();

    // Gather quantized rows + scatter dw
    for (int i = tid; i < 128 * (D / 4); i += 256) {
        int row = i >> 6;
        int c4  = (i & 63) << 2;
        int b   = s.bestI[row];
        float4 q = *(const float4*)(CB + (size_t)b * D + c4);
        *(float4*)(outQ + (size_t)(tok0 + row) * D + c4) = q;
        float4 xv = *(const float4*)(X + (size_t)(tok0 + row) * D + c4);
        float* dwp = g_dw + (size_t)b * D + c4;
        atomicAdd(dwp + 0, xv.x);
        atomicAdd(dwp + 1, xv.y);
        atomicAdd(dwp + 2, xv.z);
        atomicAdd(dwp + 3, xv.w);
    }
}

// ---------------------------------------------------------------------------
__global__ void vq_finalize(const float* __restrict__ ecs,
                            float* __restrict__ out_cs,
                            float* __restrict__ out_perp,
                            float* __restrict__ out_loss)
{
    __shared__ float sbuf[K];
    int k = threadIdx.x;
    float cnt = g_counts[k];
    float cn = 0.99f * ecs[k] + 0.01f * cnt;

    sbuf[k] = cn;
    __syncthreads();
    for (int st = K / 2; st > 0; st >>= 1) {
        if (k < st) sbuf[k] += sbuf[k + st];
        __syncthreads();
    }
    float ntot = sbuf[0];
    __syncthreads();

    out_cs[k] = (cn + 1e-5f) / (ntot + 0.01024f) * ntot;

    float p = cnt * (1.0f / 65536.0f);
    sbuf[k] = p * logf(p + 1e-10f);
    __syncthreads();
    for (int st = K / 2; st > 0; st >>= 1) {
        if (k < st) sbuf[k] += sbuf[k + st];
        __syncthreads();
    }
    if (k == 0) {
        out_perp[0] = expf(-sbuf[0]);
        double loss = (double)g_loss * (1.0 / 1048576.0) / (65536.0 * 256.0);
        out_loss[0] = 0.25f * (float)loss;
    }
}

__global__ void vq_ema(const float* __restrict__ emaw,
                       const float* __restrict__ ncs,
                       float* __restrict__ outE,
                       float* __restrict__ outW)
{
    int i = blockIdx.x * blockDim.x + threadIdx.x;
    float w = 0.99f * emaw[i] + 0.01f * g_dw[i];
    outE[i] = w;
    outW[i] = w / ncs[i >> 8];
}

// ---------------------------------------------------------------------------
extern "C" void kernel_launch(void* const* d_in, const int* in_sizes, int n_in,
                              void* d_out, int out_size)
{
    const float* X   = (const float*)d_in[0];
    const float* CB  = (const float*)d_in[1];
    const float* ECS = (const float*)d_in[2];
    const float* EW  = (const float*)d_in[3];
    float* out = (float*)d_out;

    const size_t OQ = 0;
    const size_t OL = (size_t)N_TOK * D;
    const size_t OI = OL + 1;
    const size_t OP = OI + N_TOK;
    const size_t OC = OP + 1;
    const size_t OE = OC + K;
    const size_t OW = OE + (size_t)K * D;

    cudaFuncSetAttribute(vq_dist, cudaFuncAttributeMaxDynamicSharedMemorySize,
                         (int)sizeof(SmemT));

    vq_prep<<<(K * D + 255) / 256, 256>>>();
    vq_cvtH<<<(N_TOK * D / 8) / 256, 256>>>(X, g_xf);
    vq_cvtCT<<<K / 128, 256>>>(CB, g_ct);
    vq_cs<<<K / 8, 256>>>(CB);
    vq_dist<<<N_TOK / 128, 256, sizeof(SmemT)>>>(X, CB, out + OQ, out + OI);
    vq_finalize<<<1, K>>>(ECS, out + OC, out + OP, out + OL);
    vq_ema<<<(K * D) / 256, 256>>>(EW, out + OC, out + OE, out + OW);
}

// round 17
// speedup vs baseline: 18.4555x; 18.4555x over previous
#include <cuda_runtime.h>
#include <stdint.h>

// Problem constants
#define N_TOK 65536
#define D     256
#define K     1024

// GEMM tiling
#define BM 128
#define BN 128
#define BK 16
#define TM 8
#define TN 8

// Packed fp32x2 FMA (exact per-lane fp32 FMA; measured ~neutral-to-slightly-
// positive vs scalar FFMA on this target — kept from the 952us baseline)
#define FMA_F32X2(d, a, b, c) \
    asm("fma.rn.f32x2 %0, %1, %2, %3;" : "=l"(d) : "l"(a), "l"(b), "l"(c))
#define PACK_DUP_F32X2(out, f) \
    asm("mov.b64 %0, {%1, %1};" : "=l"(out) : "r"(__float_as_uint(f)))
#define UNPACK_F32X2(lo, hi, in) \
    asm("mov.b64 {%0, %1}, %2;" : "=f"(lo), "=f"(hi) : "l"(in))

// Scratch (no cudaMalloc allowed)
__device__ float g_counts[K];
__device__ float g_dw[K * D];
__device__ float g_cs[K];
__device__ unsigned long long g_loss;

// ---------------------------------------------------------------------------
// Fused init: zero scratch + codebook squared norms.
// cs per-row summation kept BITWISE IDENTICAL to the passing rounds
// (warp per row, lane*8 float4 order) — it feeds the distance fp32 grid.
// ---------------------------------------------------------------------------
__global__ void vq_init(const float* __restrict__ CB) {
    int tid = threadIdx.x;
    int gi  = blockIdx.x * 256 + tid;          // 0 .. 32767

    // zero g_dw (8 floats per thread), counts, loss
    float4 z = make_float4(0.f, 0.f, 0.f, 0.f);
    *(float4*)(g_dw + (size_t)gi * 8)     = z;
    *(float4*)(g_dw + (size_t)gi * 8 + 4) = z;
    if (gi < K)  g_counts[gi] = 0.0f;
    if (gi == 0) g_loss = 0ull;

    // codebook norms: one warp per row (8 rows per block)
    int w = blockIdx.x * 8 + (tid >> 5);
    int lane = tid & 31;
    if (w < K) {
        const float* row = CB + (size_t)w * D + lane * 8;
        float4 v0 = *(const float4*)row;
        float4 v1 = *(const float4*)(row + 4);
        float s = v0.x * v0.x + v0.y * v0.y + v0.z * v0.z + v0.w * v0.w
                + v1.x * v1.x + v1.y * v1.y + v1.z * v1.z + v1.w * v1.w;
        #pragma unroll
        for (int o = 16; o > 0; o >>= 1) s += __shfl_xor_sync(0xffffffffu, s, o);
        if (lane == 0) g_cs[w] = s;
    }
}

// ---------------------------------------------------------------------------
// Main fused kernel: distance GEMM (double-buffered) + argmin + epilogues
// ---------------------------------------------------------------------------
__global__ __launch_bounds__(256, 2) void vq_main(
    const float* __restrict__ X, const float* __restrict__ CB,
    float* __restrict__ outQ, float* __restrict__ outIdx)
{
    // Tiles and the post-GEMM reduction arrays never live at the same time.
    __shared__ union {
        struct {
            float As[2][BK][BM];
            float Bs[2][BK][BN];
        } g;                                  // 32 KB (double-buffered)
        struct {
            float red_d[16][BM];
            int   red_i[16][BM];
        } r;                                  // 16 KB
    } u;
    __shared__ float rxs[BM];
    __shared__ int   bestI[BM];
    __shared__ float bestD[BM];

    const int tid = threadIdx.x;
    const int tx = tid & 15;       // code-column group
    const int ty = tid >> 4;       // token-row group
    const int tok0 = blockIdx.x * BM;

    // Staging coordinates (each thread loads rows sr and sr+64, cols scg..+3)
    const int sr  = tid >> 2;          // 0..63
    const int scg = (tid & 3) << 2;    // 0,4,8,12

    // Per-token ||x||^2 (identical order to all passing rounds)
    if (tid < BM) {
        const float* xr = X + (size_t)(tok0 + tid) * D;
        float s = 0.0f;
        #pragma unroll 8
        for (int j = 0; j < D; j += 4) {
            float4 v = *(const float4*)(xr + j);
            s += v.x * v.x; s += v.y * v.y; s += v.z * v.z; s += v.w * v.w;
        }
        rxs[tid] = s;
    }

    float bd[TM];
    int   bi[TM];
    #pragma unroll
    for (int r = 0; r < TM; r++) { bd[r] = 3.4e38f; bi[r] = 0; }

    __syncthreads();

    const float* Xa = X  + (size_t)(tok0 + sr) * D + scg;
    const float* Xb = X  + (size_t)(tok0 + sr + 64) * D + scg;

    for (int kc = 0; kc < K / BN; kc++) {
        const float* Ca = CB + (size_t)(kc * BN + sr) * D + scg;
        const float* Cb = CB + (size_t)(kc * BN + sr + 64) * D + scg;

        unsigned long long acc2[TM][TN / 2];
        #pragma unroll
        for (int r = 0; r < TM; r++)
            #pragma unroll
            for (int c = 0; c < TN / 2; c++) acc2[r][c] = 0ull;

        // Prologue: stage dd=0 into buffer 0
        {
            float4 a0 = *(const float4*)(Xa);
            float4 a1 = *(const float4*)(Xb);
            float4 b0 = *(const float4*)(Ca);
            float4 b1 = *(const float4*)(Cb);
            u.g.As[0][scg + 0][sr] = a0.x; u.g.As[0][scg + 1][sr] = a0.y;
            u.g.As[0][scg + 2][sr] = a0.z; u.g.As[0][scg + 3][sr] = a0.w;
            u.g.As[0][scg + 0][sr + 64] = a1.x; u.g.As[0][scg + 1][sr + 64] = a1.y;
            u.g.As[0][scg + 2][sr + 64] = a1.z; u.g.As[0][scg + 3][sr + 64] = a1.w;
            u.g.Bs[0][scg + 0][sr] = b0.x; u.g.Bs[0][scg + 1][sr] = b0.y;
            u.g.Bs[0][scg + 2][sr] = b0.z; u.g.Bs[0][scg + 3][sr] = b0.w;
            u.g.Bs[0][scg + 0][sr + 64] = b1.x; u.g.Bs[0][scg + 1][sr + 64] = b1.y;
            u.g.Bs[0][scg + 2][sr + 64] = b1.z; u.g.Bs[0][scg + 3][sr + 64] = b1.w;
        }
        __syncthreads();

        #pragma unroll 1
        for (int t = 0; t < D / BK; t++) {
            const int buf = t & 1;
            float4 a0, a1, b0, b1;
            const bool more = (t + 1 < D / BK);
            if (more) {
                int dd = (t + 1) * BK;
                a0 = *(const float4*)(Xa + dd);
                a1 = *(const float4*)(Xb + dd);
                b0 = *(const float4*)(Ca + dd);
                b1 = *(const float4*)(Cb + dd);
            }

            #pragma unroll
            for (int k = 0; k < BK; k++) {
                float a_[TM];
                *(float4*)(a_)     = *(const float4*)&u.g.As[buf][k][ty * TM];
                *(float4*)(a_ + 4) = *(const float4*)&u.g.As[buf][k][ty * TM + 4];
                ulonglong2 b01 = *(const ulonglong2*)&u.g.Bs[buf][k][tx * TN];
                ulonglong2 b23 = *(const ulonglong2*)&u.g.Bs[buf][k][tx * TN + 4];
                #pragma unroll
                for (int r = 0; r < TM; r++) {
                    unsigned long long pa;
                    PACK_DUP_F32X2(pa, a_[r]);
                    FMA_F32X2(acc2[r][0], pa, b01.x, acc2[r][0]);
                    FMA_F32X2(acc2[r][1], pa, b01.y, acc2[r][1]);
                    FMA_F32X2(acc2[r][2], pa, b23.x, acc2[r][2]);
                    FMA_F32X2(acc2[r][3], pa, b23.y, acc2[r][3]);
                }
            }

            if (more) {
                const int nb = buf ^ 1;
                u.g.As[nb][scg + 0][sr] = a0.x; u.g.As[nb][scg + 1][sr] = a0.y;
                u.g.As[nb][scg + 2][sr] = a0.z; u.g.As[nb][scg + 3][sr] = a0.w;
                u.g.As[nb][scg + 0][sr + 64] = a1.x; u.g.As[nb][scg + 1][sr + 64] = a1.y;
                u.g.As[nb][scg + 2][sr + 64] = a1.z; u.g.As[nb][scg + 3][sr + 64] = a1.w;
                u.g.Bs[nb][scg + 0][sr] = b0.x; u.g.Bs[nb][scg + 1][sr] = b0.y;
                u.g.Bs[nb][scg + 2][sr] = b0.z; u.g.Bs[nb][scg + 3][sr] = b0.w;
                u.g.Bs[nb][scg + 0][sr + 64] = b1.x; u.g.Bs[nb][scg + 1][sr + 64] = b1.y;
                u.g.Bs[nb][scg + 2][sr + 64] = b1.z; u.g.Bs[nb][scg + 3][sr + 64] = b1.w;
            }
            __syncthreads();
        }

        // Chunk epilogue: d = (rx + cs) - 2*dot ; running argmin (strict <,
        // k ascending -> first-index tie-break within this thread)
        #pragma unroll
        for (int c2 = 0; c2 < TN / 2; c2++) {
            int kidx = kc * BN + tx * TN + 2 * c2;
            float cs0 = g_cs[kidx];
            float cs1 = g_cs[kidx + 1];
            #pragma unroll
            for (int r = 0; r < TM; r++) {
                float lo, hi;
                UNPACK_F32X2(lo, hi, acc2[r][c2]);
                float rx = rxs[ty * TM + r];
                float d0 = (rx + cs0) - 2.0f * lo;
                float d1 = (rx + cs1) - 2.0f * hi;
                if (d0 < bd[r]) { bd[r] = d0; bi[r] = kidx; }
                if (d1 < bd[r]) { bd[r] = d1; bi[r] = kidx + 1; }
            }
        }
    }
    __syncthreads();   // tiles dead; union switches to reduction arrays

    // Cross-thread argmin reduce (16 tx threads share each token row)
    #pragma unroll
    for (int r = 0; r < TM; r++) {
        u.r.red_d[tx][ty * TM + r] = bd[r];
        u.r.red_i[tx][ty * TM + r] = bi[r];
    }
    __syncthreads();

    if (tid < BM) {
        float best = 3.4e38f;
        int bidx = K;
        #pragma unroll
        for (int t = 0; t < 16; t++) {
            float d = u.r.red_d[t][tid];
            int   ii = u.r.red_i[t][tid];
            if (d < best || (d == best && ii < bidx)) { best = d; bidx = ii; }
        }
        bestI[tid] = bidx;
        bestD[tid] = best;
        outIdx[tok0 + tid] = (float)bidx;
        atomicAdd(&g_counts[bidx], 1.0f);   // exact: integer-valued fp32 sums
    }
    __syncthreads();

    // Deterministic loss accumulation: scaled int64
    if (tid == 0) {
        double s = 0.0;
        for (int r = 0; r < BM; r++) s += (double)bestD[r];
        atomicAdd(&g_loss, (unsigned long long)llrint(s * 1048576.0));
    }

    // Gather quantized rows + scatter dw
    for (int i = tid; i < BM * (D / 4); i += 256) {
        int row = i >> 6;
        int c4  = (i & 63) << 2;
        int b   = bestI[row];
        float4 q = *(const float4*)(CB + (size_t)b * D + c4);
        *(float4*)(outQ + (size_t)(tok0 + row) * D + c4) = q;
        float4 xv = *(const float4*)(X + (size_t)(tok0 + row) * D + c4);
        float* dwp = g_dw + (size_t)b * D + c4;
        atomicAdd(dwp + 0, xv.x);
        atomicAdd(dwp + 1, xv.y);
        atomicAdd(dwp + 2, xv.z);
        atomicAdd(dwp + 3, xv.w);
    }
}

// ---------------------------------------------------------------------------
// Finalize: new_cs (Laplace-smoothed), perplexity, vq_loss. One block, K thr.
// ---------------------------------------------------------------------------
__global__ void vq_finalize(const float* __restrict__ ecs,
                            float* __restrict__ out_cs,
                            float* __restrict__ out_perp,
                            float* __restrict__ out_loss)
{
    __shared__ float sbuf[K];
    int k = threadIdx.x;
    float cnt = g_counts[k];
    float cn = 0.99f * ecs[k] + 0.01f * cnt;

    sbuf[k] = cn;
    __syncthreads();
    for (int s = K / 2; s > 0; s >>= 1) {
        if (k < s) sbuf[k] += sbuf[k + s];
        __syncthreads();
    }
    float ntot = sbuf[0];
    __syncthreads();

    out_cs[k] = (cn + 1e-5f) / (ntot + 0.01024f) * ntot;

    float p = cnt * (1.0f / 65536.0f);
    sbuf[k] = p * logf(p + 1e-10f);
    __syncthreads();
    for (int s = K / 2; s > 0; s >>= 1) {
        if (k < s) sbuf[k] += sbuf[k + s];
        __syncthreads();
    }
    if (k == 0) {
        out_perp[0] = expf(-sbuf[0]);
        double loss = (double)g_loss * (1.0 / 1048576.0) / (65536.0 * 256.0);
        out_loss[0] = 0.25f * (float)loss;
    }
}

// ---------------------------------------------------------------------------
// EMA codebook update + normalized weight
// ---------------------------------------------------------------------------
__global__ void vq_ema(const float* __restrict__ emaw,
                       const float* __restrict__ ncs,
                       float* __restrict__ outE,
                       float* __restrict__ outW)
{
    int i = blockIdx.x * blockDim.x + threadIdx.x;   // < K*D
    float w = 0.99f * emaw[i] + 0.01f * g_dw[i];
    outE[i] = w;
    outW[i] = w / ncs[i >> 8];
}

// ---------------------------------------------------------------------------
// Launch: outputs concatenated in reference return order, all float32:
//   quantized_st [N*D] | vq_loss [1] | indices [N] | perplexity [1]
//   | new_cs [K] | new_ema_w [K*D] | new_weight [K*D]
// ---------------------------------------------------------------------------
extern "C" void kernel_launch(void* const* d_in, const int* in_sizes, int n_in,
                              void* d_out, int out_size)
{
    const float* X   = (const float*)d_in[0];   // inputs  [N, D]
    const float* CB  = (const float*)d_in[1];   // codebook [K, D]
    const float* ECS = (const float*)d_in[2];   // ema_cluster_size [K]
    const float* EW  = (const float*)d_in[3];   // ema_w [K, D]
    float* out = (float*)d_out;

    const size_t OQ = 0;
    const size_t OL = (size_t)N_TOK * D;        // vq_loss
    const size_t OI = OL + 1;                   // indices
    const size_t OP = OI + N_TOK;               // perplexity
    const size_t OC = OP + 1;                   // new_cs
    const size_t OE = OC + K;                   // new_ema_w
    const size_t OW = OE + (size_t)K * D;       // new_weight

    vq_init<<<K / 8, 256>>>(CB);
    vq_main<<<N_TOK / BM, 256>>>(X, CB, out + OQ, out + OI);
    vq_finalize<<<1, K>>>(ECS, out + OC, out + OP, out + OL);
    vq_ema<<<(K * D) / 256, 256>>>(EW, out + OC, out + OE, out + OW);
}